// round 16
// baseline (speedup 1.0000x reference)
#include <cuda_runtime.h>
#include <cuda_fp16.h>

// out[b, o] = max_i min(x[b, i], W[i, o])   (fuzzy max-min composition)
// x: [1024, 512] f32, W: [512, 512] f32, out: [1024, 512] f32.
//
// R16: classification hoisted into the prepass.
//   Prep (one launch): W -> packed half2; per row b, compacted candidate
//   list g_meta[b] = {w-row offset, dup-half2 x} with G1 (x>=0.875) then
//   G2 (0.75<=x<0.875), 16 zero pads, counts in g_cnt[b].
//   Main: speculatively load header + 192 meta entries (known addresses,
//   full MLP), one barrier, then candidate-parallel W scan (R13 layout:
//   4 warps x 4 rows/round, lane owns 16 outputs, 2x LDG.128/row).
//   Tiers: exit at best>=0.875 after G1, best>=0.75 after G2 (fp16-exact
//   thresholds, monotone rounding); dense 512-row fallback for any other
//   case (incl. C1+C2>192) keeps arbitrary inputs correct.

#define B_DIM   1024
#define IN_F    512
#define OUT_F   512
#define THREADS 128
#define TH1     0.875f
#define TH2     0.75f
#define MSTRIDE 528        // meta slots per row (512 + 16 pad)
#define MPRE    192        // speculative preload depth

// scratch: w packed-half2 [k][n/2]  (512 KB, L2-resident)
__device__ __align__(16) unsigned g_wh[IN_F * OUT_F / 2];
// scratch: per-row compacted candidates {w elem-offset, dup-half2 x}
__device__ __align__(16) uint2 g_meta[B_DIM * MSTRIDE];   // 4.3 MB
__device__ uint2 g_cnt[B_DIM];                            // {C1, C2}

// ================= prepass =================
// blocks [0,128): W f32 -> packed half2 (4KB chunks)
// blocks [128,256): x classify, 8 rows per block (warp per row)
__global__ __launch_bounds__(256)
void prep_kernel(const float* __restrict__ x, const float* __restrict__ w)
{
    const int t = threadIdx.x;

    if (blockIdx.x < 128) {
        const int f4base = blockIdx.x * 512 + t * 2;
        float4 a = ((const float4*)w)[f4base];
        float4 b = ((const float4*)w)[f4base + 1];
        __half2 h0 = __floats2half2_rn(a.x, a.y);
        __half2 h1 = __floats2half2_rn(a.z, a.w);
        __half2 h2 = __floats2half2_rn(b.x, b.y);
        __half2 h3 = __floats2half2_rn(b.z, b.w);
        ((uint4*)g_wh)[blockIdx.x * 256 + t] = make_uint4(
            *(unsigned*)&h0, *(unsigned*)&h1, *(unsigned*)&h2, *(unsigned*)&h3);
        return;
    }

    // ---- x classify: warp per row ----
    const int warp = t >> 5;
    const int lane = t & 31;
    const int r    = (blockIdx.x - 128) * 8 + warp;
    const unsigned lmlt = (1u << lane) - 1u;

    float xv[16];
    unsigned M1[16], M2[16];
#pragma unroll
    for (int c = 0; c < 16; c++) {
        float v = x[r * IN_F + c * 32 + lane];
        xv[c] = v;
        M1[c] = __ballot_sync(0xFFFFFFFFu, v >= TH1);
        M2[c] = __ballot_sync(0xFFFFFFFFu, (v >= TH2) && (v < TH1));
    }
    uint2* mrow = &g_meta[r * MSTRIDE];
    int c1 = 0;
#pragma unroll
    for (int c = 0; c < 16; c++) {             // pass 1: G1
        if (xv[c] >= TH1) {
            int idx = c * 32 + lane;
            __half2 d = __float2half2_rn(xv[c]);
            mrow[c1 + __popc(M1[c] & lmlt)] =
                make_uint2((unsigned)(idx * (OUT_F / 2)), *(unsigned*)&d);
        }
        c1 += __popc(M1[c]);
    }
    int c2 = 0;
#pragma unroll
    for (int c = 0; c < 16; c++) {             // pass 2: G2 after G1
        if ((xv[c] >= TH2) && (xv[c] < TH1)) {
            int idx = c * 32 + lane;
            __half2 d = __float2half2_rn(xv[c]);
            mrow[c1 + c2 + __popc(M2[c] & lmlt)] =
                make_uint2((unsigned)(idx * (OUT_F / 2)), *(unsigned*)&d);
        }
        c2 += __popc(M2[c]);
    }
    if (lane < 16) mrow[c1 + c2 + lane] = make_uint2(0u, 0u);  // zero pad
    if (lane == 0) g_cnt[r] = make_uint2((unsigned)c1, (unsigned)c2);
}

// ================= main =================
__global__ __launch_bounds__(THREADS, 8)
void maxmin_cp(const float* __restrict__ x, float* __restrict__ out)
{
    __shared__ uint2    smeta[MPRE];        // 1.5 KB
    __shared__ unsigned mrg[4][OUT_F / 2];  // 4 KB

    const int t    = threadIdx.x;
    const int b    = blockIdx.x;
    const int warp = t >> 5;
    const int lane = t & 31;

    // ---- speculative loads: header (broadcast) + 192 meta entries ----
    uint2 hdr = g_cnt[b];
    const uint2* mrow = &g_meta[b * MSTRIDE];
    uint2 e0 = mrow[t];
    uint2 e1 = (t < MPRE - THREADS) ? mrow[THREADS + t] : make_uint2(0u, 0u);
    smeta[t] = e0;
    if (t < MPRE - THREADS) smeta[THREADS + t] = e1;
    __syncthreads();

    const int C1 = (int)hdr.x;
    const int C2 = (int)hdr.y;

    // lane owns 16 outputs: uints co..co+7 of a packed W row (2x LDG.128)
    const int co = lane * 8;
    __half2 acc[8];
#pragma unroll
    for (int i = 0; i < 8; i++) acc[i] = __float2half2_rn(0.f);

    auto scan_rows = [&](int rbeg, int nit) {
#pragma unroll 1
        for (int it = 0; it < nit; it++) {
            const int rb = rbeg + it * 16 + warp * 4;
            uint4 v[8];
            unsigned xh[4];
#pragma unroll
            for (int q = 0; q < 4; q++) {          // 8 independent LDG.128
                uint2 m = smeta[rb + q];
                xh[q] = m.y;
                const uint4* p = (const uint4*)&g_wh[m.x + co];
                v[2 * q]     = p[0];
                v[2 * q + 1] = p[1];
            }
#pragma unroll
            for (int q = 0; q < 4; q++) {
                __half2 xw = *(__half2*)&xh[q];
                acc[0] = __hmax2(acc[0], __hmin2(xw, *(__half2*)&v[2*q].x));
                acc[1] = __hmax2(acc[1], __hmin2(xw, *(__half2*)&v[2*q].y));
                acc[2] = __hmax2(acc[2], __hmin2(xw, *(__half2*)&v[2*q].z));
                acc[3] = __hmax2(acc[3], __hmin2(xw, *(__half2*)&v[2*q].w));
                acc[4] = __hmax2(acc[4], __hmin2(xw, *(__half2*)&v[2*q+1].x));
                acc[5] = __hmax2(acc[5], __hmin2(xw, *(__half2*)&v[2*q+1].y));
                acc[6] = __hmax2(acc[6], __hmin2(xw, *(__half2*)&v[2*q+1].z));
                acc[7] = __hmax2(acc[7], __hmin2(xw, *(__half2*)&v[2*q+1].w));
            }
        }
    };

    auto merge_read = [&](__half2& best0, __half2& best1) {
        *(uint4*)&mrg[warp][co] =
            make_uint4(*(unsigned*)&acc[0], *(unsigned*)&acc[1],
                       *(unsigned*)&acc[2], *(unsigned*)&acc[3]);
        *(uint4*)&mrg[warp][co + 4] =
            make_uint4(*(unsigned*)&acc[4], *(unsigned*)&acc[5],
                       *(unsigned*)&acc[6], *(unsigned*)&acc[7]);
        __syncthreads();
        uint2 r0 = *(const uint2*)&mrg[0][2 * t];
        uint2 r1 = *(const uint2*)&mrg[1][2 * t];
        uint2 r2 = *(const uint2*)&mrg[2][2 * t];
        uint2 r3 = *(const uint2*)&mrg[3][2 * t];
        best0 = __hmax2(__hmax2(*(__half2*)&r0.x, *(__half2*)&r1.x),
                        __hmax2(*(__half2*)&r2.x, *(__half2*)&r3.x));
        best1 = __hmax2(__hmax2(*(__half2*)&r0.y, *(__half2*)&r1.y),
                        __hmax2(*(__half2*)&r2.y, *(__half2*)&r3.y));
    };

    __half2 best0 = __float2half2_rn(0.f), best1 = best0;
    bool need_dense = (C1 + C2 > MPRE);

    if (!need_dense) {
        // ---- tier 1 ----
        const int nit1 = (C1 + 15) >> 4;
        scan_rows(0, nit1);
        merge_read(best0, best1);
        const __half2 T1h = __float2half2_rn(TH1);
        bool pass = __hbge2(best0, T1h) && __hbge2(best1, T1h);
        if (!__syncthreads_and(pass)) {
            // ---- tier 2 ----
            const int done = nit1 * 16;
            const int rem  = C1 + C2 - done;
            if (rem > 0) scan_rows(done, (rem + 15) >> 4);
            merge_read(best0, best1);
            const __half2 T2h = __float2half2_rn(TH2);
            pass = __hbge2(best0, T2h) && __hbge2(best1, T2h);
            if (!__syncthreads_and(pass)) need_dense = true;
        }
    }

    if (need_dense) {
        // ---- dense fallback (arbitrary inputs; ~never for uniform) ----
        const int te = t * 2;
#pragma unroll 8
        for (int j = 0; j < IN_F; j++) {
            uint2 wv = *(const uint2*)&g_wh[j * (OUT_F / 2) + te];
            __half2 xh = __float2half2_rn(__ldg(&x[b * IN_F + j]));
            best0 = __hmax2(best0, __hmin2(xh, *(__half2*)&wv.x));
            best1 = __hmax2(best1, __hmin2(xh, *(__half2*)&wv.y));
        }
    }

    // ---- store 4 outputs (float4, coalesced) ----
    float2 a = __half22float2(best0);
    float2 d = __half22float2(best1);
    *(float4*)(out + b * OUT_F + t * 4) = make_float4(a.x, a.y, d.x, d.y);
}

extern "C" void kernel_launch(void* const* d_in, const int* in_sizes, int n_in,
                              void* d_out, int out_size)
{
    const float* x = (const float*)d_in[0];   // [1024, 512]
    const float* w = (const float*)d_in[1];   // [512, 512]
    float* out = (float*)d_out;               // [1024, 512]

    prep_kernel<<<256, 256>>>(x, w);
    maxmin_cp<<<B_DIM, THREADS>>>(x, out);
}

// round 17
// speedup vs baseline: 1.1555x; 1.1555x over previous
#include <cuda_runtime.h>
#include <cuda_fp16.h>

// out[b, o] = max_i min(x[b, i], W[i, o])   (fuzzy max-min composition)
// x: [1024, 512] f32, W: [512, 512] f32, out: [1024, 512] f32.
//
// R17: R16's main kernel (hoisted classification; speculative meta preload;
// candidate-parallel scan) + a WIDE prepass: 2048 single-warp blocks
// (13.8/SM) instead of 256 fat blocks (1.7/SM). R16's prep was latency-
// bound and ate the main-kernel win; classification itself is ~0.5us of
// bandwidth. Tier structure: G1 (x>=0.875), G2 (0.75<=x<0.875), exits at
// fp16-exact thresholds (monotone rounding => sound), dense fallback for
// anything else (incl. C1+C2>192) keeps arbitrary inputs correct.

#define B_DIM   1024
#define IN_F    512
#define OUT_F   512
#define THREADS 128
#define TH1     0.875f
#define TH2     0.75f
#define MSTRIDE 528        // meta slots per row (512 + 16 pad)
#define MPRE    192        // speculative preload depth

// scratch: w packed-half2 [k][n/2]  (512 KB, L2-resident)
__device__ __align__(16) unsigned g_wh[IN_F * OUT_F / 2];
// scratch: per-row compacted candidates {w elem-offset, dup-half2 x}
__device__ __align__(16) uint2 g_meta[B_DIM * MSTRIDE];
__device__ uint2 g_cnt[B_DIM];                            // {C1, C2}

// ================= prepass: 2048 single-warp blocks =================
// blocks [0,1024):    W f32 -> packed half2 (64 float4 per block, coalesced)
// blocks [1024,2048): classify row (bid-1024), one warp
__global__ __launch_bounds__(32)
void prep_kernel(const float* __restrict__ x, const float* __restrict__ w)
{
    const int lane = threadIdx.x;

    if (blockIdx.x < 1024) {
        // ---- W convert: 2 coalesced float4 reads -> 2 coalesced uint2 writes
        const int base = blockIdx.x * 64;              // float4 index
        float4 a = ((const float4*)w)[base + lane];
        float4 b = ((const float4*)w)[base + 32 + lane];
        __half2 a0 = __floats2half2_rn(a.x, a.y);
        __half2 a1 = __floats2half2_rn(a.z, a.w);
        __half2 b0 = __floats2half2_rn(b.x, b.y);
        __half2 b1 = __floats2half2_rn(b.z, b.w);
        ((uint2*)g_wh)[base + lane]      = make_uint2(*(unsigned*)&a0, *(unsigned*)&a1);
        ((uint2*)g_wh)[base + 32 + lane] = make_uint2(*(unsigned*)&b0, *(unsigned*)&b1);
        return;
    }

    // ---- classify one row ----
    const int r = blockIdx.x - 1024;
    const unsigned lmlt = (1u << lane) - 1u;

    float xv[16];
    unsigned M1[16], M2[16];
#pragma unroll
    for (int c = 0; c < 16; c++) {
        float v = x[r * IN_F + c * 32 + lane];
        xv[c] = v;
        M1[c] = __ballot_sync(0xFFFFFFFFu, v >= TH1);
        M2[c] = __ballot_sync(0xFFFFFFFFu, (v >= TH2) && (v < TH1));
    }
    uint2* mrow = &g_meta[r * MSTRIDE];
    int c1 = 0;
#pragma unroll
    for (int c = 0; c < 16; c++) {             // pass 1: G1
        if (xv[c] >= TH1) {
            int idx = c * 32 + lane;
            __half2 d = __float2half2_rn(xv[c]);
            mrow[c1 + __popc(M1[c] & lmlt)] =
                make_uint2((unsigned)(idx * (OUT_F / 2)), *(unsigned*)&d);
        }
        c1 += __popc(M1[c]);
    }
    int c2 = 0;
#pragma unroll
    for (int c = 0; c < 16; c++) {             // pass 2: G2 after G1
        if ((xv[c] >= TH2) && (xv[c] < TH1)) {
            int idx = c * 32 + lane;
            __half2 d = __float2half2_rn(xv[c]);
            mrow[c1 + c2 + __popc(M2[c] & lmlt)] =
                make_uint2((unsigned)(idx * (OUT_F / 2)), *(unsigned*)&d);
        }
        c2 += __popc(M2[c]);
    }
    if (lane < 16) mrow[c1 + c2 + lane] = make_uint2(0u, 0u);  // zero pad
    if (lane == 0) g_cnt[r] = make_uint2((unsigned)c1, (unsigned)c2);
}

// ================= main (R16, unchanged) =================
__global__ __launch_bounds__(THREADS, 8)
void maxmin_cp(const float* __restrict__ x, float* __restrict__ out)
{
    __shared__ uint2    smeta[MPRE];        // 1.5 KB
    __shared__ unsigned mrg[4][OUT_F / 2];  // 4 KB

    const int t    = threadIdx.x;
    const int b    = blockIdx.x;
    const int warp = t >> 5;
    const int lane = t & 31;

    // ---- speculative loads: header (broadcast) + 192 meta entries ----
    uint2 hdr = g_cnt[b];
    const uint2* mrow = &g_meta[b * MSTRIDE];
    uint2 e0 = mrow[t];
    uint2 e1 = (t < MPRE - THREADS) ? mrow[THREADS + t] : make_uint2(0u, 0u);
    smeta[t] = e0;
    if (t < MPRE - THREADS) smeta[THREADS + t] = e1;
    __syncthreads();

    const int C1 = (int)hdr.x;
    const int C2 = (int)hdr.y;

    // lane owns 16 outputs: uints co..co+7 of a packed W row (2x LDG.128)
    const int co = lane * 8;
    __half2 acc[8];
#pragma unroll
    for (int i = 0; i < 8; i++) acc[i] = __float2half2_rn(0.f);

    auto scan_rows = [&](int rbeg, int nit) {
#pragma unroll 1
        for (int it = 0; it < nit; it++) {
            const int rb = rbeg + it * 16 + warp * 4;
            uint4 v[8];
            unsigned xh[4];
#pragma unroll
            for (int q = 0; q < 4; q++) {          // 8 independent LDG.128
                uint2 m = smeta[rb + q];
                xh[q] = m.y;
                const uint4* p = (const uint4*)&g_wh[m.x + co];
                v[2 * q]     = p[0];
                v[2 * q + 1] = p[1];
            }
#pragma unroll
            for (int q = 0; q < 4; q++) {
                __half2 xw = *(__half2*)&xh[q];
                acc[0] = __hmax2(acc[0], __hmin2(xw, *(__half2*)&v[2*q].x));
                acc[1] = __hmax2(acc[1], __hmin2(xw, *(__half2*)&v[2*q].y));
                acc[2] = __hmax2(acc[2], __hmin2(xw, *(__half2*)&v[2*q].z));
                acc[3] = __hmax2(acc[3], __hmin2(xw, *(__half2*)&v[2*q].w));
                acc[4] = __hmax2(acc[4], __hmin2(xw, *(__half2*)&v[2*q+1].x));
                acc[5] = __hmax2(acc[5], __hmin2(xw, *(__half2*)&v[2*q+1].y));
                acc[6] = __hmax2(acc[6], __hmin2(xw, *(__half2*)&v[2*q+1].z));
                acc[7] = __hmax2(acc[7], __hmin2(xw, *(__half2*)&v[2*q+1].w));
            }
        }
    };

    auto merge_read = [&](__half2& best0, __half2& best1) {
        *(uint4*)&mrg[warp][co] =
            make_uint4(*(unsigned*)&acc[0], *(unsigned*)&acc[1],
                       *(unsigned*)&acc[2], *(unsigned*)&acc[3]);
        *(uint4*)&mrg[warp][co + 4] =
            make_uint4(*(unsigned*)&acc[4], *(unsigned*)&acc[5],
                       *(unsigned*)&acc[6], *(unsigned*)&acc[7]);
        __syncthreads();
        uint2 r0 = *(const uint2*)&mrg[0][2 * t];
        uint2 r1 = *(const uint2*)&mrg[1][2 * t];
        uint2 r2 = *(const uint2*)&mrg[2][2 * t];
        uint2 r3 = *(const uint2*)&mrg[3][2 * t];
        best0 = __hmax2(__hmax2(*(__half2*)&r0.x, *(__half2*)&r1.x),
                        __hmax2(*(__half2*)&r2.x, *(__half2*)&r3.x));
        best1 = __hmax2(__hmax2(*(__half2*)&r0.y, *(__half2*)&r1.y),
                        __hmax2(*(__half2*)&r2.y, *(__half2*)&r3.y));
    };

    __half2 best0 = __float2half2_rn(0.f), best1 = best0;
    bool need_dense = (C1 + C2 > MPRE);

    if (!need_dense) {
        // ---- tier 1 ----
        const int nit1 = (C1 + 15) >> 4;
        scan_rows(0, nit1);
        merge_read(best0, best1);
        const __half2 T1h = __float2half2_rn(TH1);
        bool pass = __hbge2(best0, T1h) && __hbge2(best1, T1h);
        if (!__syncthreads_and(pass)) {
            // ---- tier 2 ----
            const int done = nit1 * 16;
            const int rem  = C1 + C2 - done;
            if (rem > 0) scan_rows(done, (rem + 15) >> 4);
            merge_read(best0, best1);
            const __half2 T2h = __float2half2_rn(TH2);
            pass = __hbge2(best0, T2h) && __hbge2(best1, T2h);
            if (!__syncthreads_and(pass)) need_dense = true;
        }
    }

    if (need_dense) {
        // ---- dense fallback (arbitrary inputs; ~never for uniform) ----
        const int te = t * 2;
#pragma unroll 8
        for (int j = 0; j < IN_F; j++) {
            uint2 wv = *(const uint2*)&g_wh[j * (OUT_F / 2) + te];
            __half2 xh = __float2half2_rn(__ldg(&x[b * IN_F + j]));
            best0 = __hmax2(best0, __hmin2(xh, *(__half2*)&wv.x));
            best1 = __hmax2(best1, __hmin2(xh, *(__half2*)&wv.y));
        }
    }

    // ---- store 4 outputs (float4, coalesced) ----
    float2 a = __half22float2(best0);
    float2 d = __half22float2(best1);
    *(float4*)(out + b * OUT_F + t * 4) = make_float4(a.x, a.y, d.x, d.y);
}

extern "C" void kernel_launch(void* const* d_in, const int* in_sizes, int n_in,
                              void* d_out, int out_size)
{
    const float* x = (const float*)d_in[0];   // [1024, 512]
    const float* w = (const float*)d_in[1];   // [512, 512]
    float* out = (float*)d_out;               // [1024, 512]

    prep_kernel<<<2048, 32>>>(x, w);
    maxmin_cp<<<B_DIM, THREADS>>>(x, out);
}